// round 9
// baseline (speedup 1.0000x reference)
#include <cuda_runtime.h>
#include <cuda_bf16.h>

#define NN 50000
#define NE 800000
#define NF 100
#define NPAIR (NE / 2)

// Folded projection vectors + scratch (no allocation allowed).
__device__ __align__(16) float g_wl[2][100];
__device__ __align__(16) float g_wr[2][100];
__device__ __align__(16) float g_we[2][200];   // [head][raw 0..99 | time 100..199]
__device__ float  g_bias[6];                   // bl0 bl1 br0 br1 be0 be1
__device__ __align__(8)  float2 g_el2[NN];     // (el_h0, el_h1)
__device__ __align__(8)  float2 g_er2[NN];
__device__ __align__(16) float4 g_acc[NN];     // {nsum0, psum0, nsum1, psum1}

__device__ __forceinline__ float warp_sum(float v) {
#pragma unroll
    for (int o = 16; o > 0; o >>= 1) v += __shfl_xor_sync(0xffffffffu, v, o);
    return v;
}

__device__ __forceinline__ float dot4(float4 a, float4 b, float acc) {
    return fmaf(a.x, b.x, fmaf(a.y, b.y, fmaf(a.z, b.z, fmaf(a.w, b.w, acc))));
}

// ---------------------------------------------------------------------------
// K0: fold fc weights/biases through attention vectors (806 warp-tasks).
// ---------------------------------------------------------------------------
__global__ void k_prep(const float* __restrict__ fcnw, const float* __restrict__ fcnb,
                       const float* __restrict__ fcew, const float* __restrict__ fceb,
                       const float* __restrict__ al, const float* __restrict__ ar,
                       const float* __restrict__ ae) {
    int w = (blockIdx.x * blockDim.x + threadIdx.x) >> 5;
    int lane = threadIdx.x & 31;
    if (w < 400) {
        const float* av = (w < 200) ? al : ar;
        int t = (w < 200) ? w : (w - 200);
        int h = t / 100, k = t % 100;
        float s = 0.f;
        for (int f = lane; f < 100; f += 32)
            s += fcnw[k * 200 + h * 100 + f] * av[h * 100 + f];
        s = warp_sum(s);
        if (lane == 0) { if (w < 200) g_wl[h][k] = s; else g_wr[h][k] = s; }
    } else if (w < 800) {
        int u = w - 400;
        int h = u / 200, j = u % 200;
        float s = 0.f;
        for (int f = lane; f < 100; f += 32)
            s += fcew[j * 200 + h * 100 + f] * ae[h * 100 + f];
        s = warp_sum(s);
        if (lane == 0) g_we[h][j] = s;
    } else if (w < 806) {
        int t = w - 800;
        int h = t & 1;
        const float* bv = (t < 4) ? fcnb : fceb;
        const float* av = (t < 2) ? al : ((t < 4) ? ar : ae);
        float s = 0.f;
        for (int f = lane; f < 100; f += 32)
            s += bv[h * 100 + f] * av[h * 100 + f];
        s = warp_sum(s);
        if (lane == 0) g_bias[t] = s;
    }
}

// ---------------------------------------------------------------------------
// K1: per-node el/er (warp per node) + zero accumulators.
// ---------------------------------------------------------------------------
__global__ void k_node(const float* __restrict__ memory) {
    int n = (blockIdx.x * blockDim.x + threadIdx.x) >> 5;
    int lane = threadIdx.x & 31;
    if (n >= NN) return;
    float l0 = 0.f, l1 = 0.f, r0 = 0.f, r1 = 0.f;
    if (lane < 25) {
        float4 v  = ((const float4*)(memory + (long long)n * NF))[lane];
        float4 a0 = ((const float4*)g_wl[0])[lane];
        float4 a1 = ((const float4*)g_wl[1])[lane];
        float4 b0 = ((const float4*)g_wr[0])[lane];
        float4 b1 = ((const float4*)g_wr[1])[lane];
        l0 = dot4(v, a0, 0.f);
        l1 = dot4(v, a1, 0.f);
        r0 = dot4(v, b0, 0.f);
        r1 = dot4(v, b1, 0.f);
    }
    l0 = warp_sum(l0); l1 = warp_sum(l1);
    r0 = warp_sum(r0); r1 = warp_sum(r1);
    if (lane == 0) {
        g_el2[n] = make_float2(l0 + g_bias[0], l1 + g_bias[1]);
        g_er2[n] = make_float2(r0 + g_bias[2], r1 + g_bias[3]);
        g_acc[n] = make_float4(0.f, 0.f, 0.f, 0.f);
    }
}

// ---------------------------------------------------------------------------
// K2: 16 lanes per edge (warp = 2 edges), grid-stride over edge pairs.
// All fold-vector constants live in registers (lane owns chunks k and 16+k).
// Edge rows streamed with one-iteration software prefetch (no smem at all).
// ---------------------------------------------------------------------------
__global__ void __launch_bounds__(256, 2)
k_edge(const float* __restrict__ eraw, const float* __restrict__ ets,
       const float* __restrict__ nts,
       const int* __restrict__ src, const int* __restrict__ dst,
       const float* __restrict__ tw, const float* __restrict__ tb) {
    const int lane = threadIdx.x & 31;
    const int k    = lane & 15;
    const int sub  = lane >> 4;            // edge-in-pair
    const int gw   = (blockIdx.x * blockDim.x + threadIdx.x) >> 5;
    const int nw   = (gridDim.x * blockDim.x) >> 5;

    const float4 Z = make_float4(0.f, 0.f, 0.f, 0.f);
    // register-resident constants: chunk c0 = k (always), c1 = 16+k (k<9)
    const float4 Ar0 = ((const float4*)g_we[0])[k];
    const float4 Ar1 = ((const float4*)g_we[1])[k];
    const float4 At0 = ((const float4*)(g_we[0] + 100))[k];
    const float4 At1 = ((const float4*)(g_we[1] + 100))[k];
    const float4 Tw0 = ((const float4*)tw)[k];
    const float4 Tb0 = ((const float4*)tb)[k];
    const bool  has1 = (k < 9);
    const int   c1   = 16 + k;
    const float4 Br0 = has1 ? ((const float4*)g_we[0])[c1] : Z;
    const float4 Br1 = has1 ? ((const float4*)g_we[1])[c1] : Z;
    const float4 Bt0 = has1 ? ((const float4*)(g_we[0] + 100))[c1] : Z;
    const float4 Bt1 = has1 ? ((const float4*)(g_we[1] + 100))[c1] : Z;
    const float4 Tw1 = has1 ? ((const float4*)tw)[c1] : Z;
    const float4 Tb1 = has1 ? ((const float4*)tb)[c1] : Z;
    const float bias0 = g_bias[4], bias1 = g_bias[5];

    const float4* er4 = (const float4*)eraw;

    int p = gw;
    if (p >= NPAIR) return;

    // prefetch pair p
    int e = p * 2 + sub;
    float4 v0 = er4[e * 25 + k];
    float4 v1 = has1 ? er4[e * 25 + c1] : Z;
    int   sc = src[e];
    int   dc = dst[e];
    float etc = ets[e];

    for (;;) {
        // issue gathers for current pair (src/dst resolved last iteration)
        float  ntsv = nts[sc];
        float2 elv  = g_el2[sc];
        float2 erv  = g_er2[dc];
        int    dcur = dc;
        float  etcur = etc;
        float4 cv0 = v0, cv1 = v1;

        // prefetch next pair (independent loads, carries the DRAM stream)
        int pn = p + nw;
        bool more = (pn < NPAIR);
        if (more) {
            int en = pn * 2 + sub;
            v0 = er4[en * 25 + k];
            v1 = has1 ? er4[en * 25 + c1] : Z;
            sc = src[en]; dc = dst[en]; etc = ets[en];
        }

        // raw-feature partial dot (independent of gathers)
        float h0 = dot4(cv0, Ar0, 0.f);
        float h1 = dot4(cv0, Ar1, 0.f);
        h0 = dot4(cv1, Br0, h0);
        h1 = dot4(cv1, Br1, h1);

        // Fourier time-encoding partial dot
        float dt = etcur - ntsv;
        float c0 = __cosf(fmaf(dt, Tw0.x, Tb0.x));
        float c1v = __cosf(fmaf(dt, Tw0.y, Tb0.y));
        float c2 = __cosf(fmaf(dt, Tw0.z, Tb0.z));
        float c3 = __cosf(fmaf(dt, Tw0.w, Tb0.w));
        h0 = fmaf(c0, At0.x, fmaf(c1v, At0.y, fmaf(c2, At0.z, fmaf(c3, At0.w, h0))));
        h1 = fmaf(c0, At1.x, fmaf(c1v, At1.y, fmaf(c2, At1.z, fmaf(c3, At1.w, h1))));
        float d0 = __cosf(fmaf(dt, Tw1.x, Tb1.x));
        float d1 = __cosf(fmaf(dt, Tw1.y, Tb1.y));
        float d2 = __cosf(fmaf(dt, Tw1.z, Tb1.z));
        float d3 = __cosf(fmaf(dt, Tw1.w, Tb1.w));
        h0 = fmaf(d0, Bt0.x, fmaf(d1, Bt0.y, fmaf(d2, Bt0.z, fmaf(d3, Bt0.w, h0))));
        h1 = fmaf(d0, Bt1.x, fmaf(d1, Bt1.y, fmaf(d2, Bt1.z, fmaf(d3, Bt1.w, h1))));

        // reduce over the 16-lane group (xor stays within the group)
#pragma unroll
        for (int o = 8; o > 0; o >>= 1) {
            h0 += __shfl_xor_sync(0xffffffffu, h0, o);
            h1 += __shfl_xor_sync(0xffffffffu, h1, o);
        }

        if (k == 0) {
            float* acc = (float*)&g_acc[dcur];
            // head 0
            float elp0 = elv.x + h0 + bias0;
            float ev0  = elp0 + erv.x;
            ev0 = ev0 > 0.f ? ev0 : 0.2f * ev0;
            float ex0 = __expf(ev0);
            atomicAdd(acc + 0, ex0);
            atomicAdd(acc + 1, ex0 * elp0);
            // head 1
            float elp1 = elv.y + h1 + bias1;
            float ev1  = elp1 + erv.y;
            ev1 = ev1 > 0.f ? ev1 : 0.2f * ev1;
            float ex1 = __expf(ev1);
            atomicAdd(acc + 2, ex1);
            atomicAdd(acc + 3, ex1 * elp1);
        }

        if (!more) break;
        p = pn;
    }
}

// ---------------------------------------------------------------------------
// K3: out = memory + 0.5*(ft0+ft1), float4 + ILP-2 (two distant halves).
// ---------------------------------------------------------------------------
#define HALF4 (NN * 25 / 2)
__global__ void k_out(const float* __restrict__ memory, float* __restrict__ out) {
    int i = blockIdx.x * blockDim.x + threadIdx.x;
    if (i >= HALF4) return;
    int j = i + HALF4;
    unsigned n0 = (unsigned)i / 25u;
    unsigned n1 = (unsigned)j / 25u;
    float4 a0 = g_acc[n0];
    float4 a1 = g_acc[n1];
    float4 m0 = ((const float4*)memory)[i];
    float4 m1 = ((const float4*)memory)[j];
    float p0 = a0.x > 0.f ? __fdividef(a0.y, a0.x) : 0.f;
    float q0 = a0.z > 0.f ? __fdividef(a0.w, a0.z) : 0.f;
    float p1 = a1.x > 0.f ? __fdividef(a1.y, a1.x) : 0.f;
    float q1 = a1.z > 0.f ? __fdividef(a1.w, a1.z) : 0.f;
    float add0 = 0.5f * (p0 + q0);
    float add1 = 0.5f * (p1 + q1);
    ((float4*)out)[i] = make_float4(m0.x + add0, m0.y + add0, m0.z + add0, m0.w + add0);
    ((float4*)out)[j] = make_float4(m1.x + add1, m1.y + add1, m1.z + add1, m1.w + add1);
}

extern "C" void kernel_launch(void* const* d_in, const int* in_sizes, int n_in,
                              void* d_out, int out_size) {
    const float* memory = (const float*)d_in[0];
    const float* node_ts = (const float*)d_in[1];
    const float* eraw   = (const float*)d_in[2];
    const float* ets    = (const float*)d_in[3];
    const float* tw     = (const float*)d_in[4];
    const float* tb     = (const float*)d_in[5];
    const float* fcnw   = (const float*)d_in[6];
    const float* fcnb   = (const float*)d_in[7];
    const float* fcew   = (const float*)d_in[8];
    const float* fceb   = (const float*)d_in[9];
    const float* al     = (const float*)d_in[10];
    const float* ar     = (const float*)d_in[11];
    const float* ae     = (const float*)d_in[12];
    const int*   src    = (const int*)d_in[13];
    const int*   dst    = (const int*)d_in[14];
    float* out = (float*)d_out;

    k_prep<<<(806 * 32 + 255) / 256, 256>>>(fcnw, fcnb, fcew, fceb, al, ar, ae);
    k_node<<<(NN * 32 + 255) / 256, 256>>>(memory);
    // 2 blocks/SM * 148 SMs = 296 blocks, 256 threads, grid-stride over pairs
    k_edge<<<296, 256>>>(eraw, ets, node_ts, src, dst, tw, tb);
    k_out<<<(HALF4 + 255) / 256, 256>>>(memory, out);
}